// round 6
// baseline (speedup 1.0000x reference)
#include <cuda_runtime.h>

// Problem constants (fixed by setup_inputs)
#define BATCH   16
#define CHAN    4
#define H_IN    128
#define W_IN    240
#define MAXD    24
#define H_OUT   1024
#define W_OUT   1920
#define W4      (W_OUT / 4)     // 480
#define GRP     240             // 8-px column groups per row

// Low-res disparity prediction scratch (pred * 8): 16*128*240 floats ≈ 2 MB.
__device__ float g_pred[BATCH * H_IN * W_IN];

// ---------------------------------------------------------------------------
// K1: cost volume + softmax expectation. One block per (b, y) row.
// Channel-packed float4 smem; unshifted softmax (cost >= 0, no overflow).
// ---------------------------------------------------------------------------
__global__ __launch_bounds__(256) void disp_kernel(
    const float* __restrict__ fl, const float* __restrict__ fr)
{
    const int row = blockIdx.x;          // b*H_IN + y
    const int b = row >> 7;
    const int y = row & (H_IN - 1);

    __shared__ float4 sl4[W_IN];
    __shared__ float4 sr4[W_IN];

    const size_t rbase = ((size_t)b * CHAN) * (H_IN * W_IN) + (size_t)y * W_IN;
    for (int i = threadIdx.x; i < 2 * CHAN * W_IN; i += 256) {
        const int x   = i % W_IN;
        const int t   = i / W_IN;       // 0..7
        const int c   = t & 3;
        const int img = t >> 2;
        const size_t off = rbase + (size_t)c * (H_IN * W_IN) + x;
        const float v = img ? fr[off] : fl[off];
        float* dst = img ? (float*)&sr4[x] : (float*)&sl4[x];
        dst[c] = v;
    }
    __syncthreads();

    const int x = threadIdx.x;
    if (x < W_IN) {
        const float4 L = sl4[x];
        const float absl = fabsf(L.x) + fabsf(L.y) + fabsf(L.z) + fabsf(L.w);

        float num = 0.0f, den = 0.0f;
#pragma unroll
        for (int d = 0; d < MAXD; d++) {
            const int xs = x - d;
            float c;
            if (xs >= 0) {
                const float4 R = sr4[xs];
                c = fabsf(L.x - R.x) + fabsf(L.y - R.y)
                  + fabsf(L.z - R.z) + fabsf(L.w - R.w);
            } else {
                c = absl;                     // zero padding
            }
            const float e = __expf(-c);       // softmax(-cost), unshifted
            den += e;
            num += (float)d * e;
        }
        g_pred[row * W_IN + x] = (num / den) * 8.0f;   // * (1024/128)
    }
}

// ---------------------------------------------------------------------------
// K2: bilinear upsample 128x240 -> 1024x1920 (align_corners).
// One thread per (b, input-row r, 8-px column group g). 491,520 threads.
// x-geometry hoisted; 6 pred loads (L2 hits) feed ~8 output rows of 8 px.
// No smem, no block syncs -> high occupancy, deep TLP.
// ---------------------------------------------------------------------------
__global__ __launch_bounds__(256) void resize_kernel(float* __restrict__ out)
{
    const int idx = blockIdx.x * 256 + threadIdx.x;   // exact grid, no guard
    const int g = idx % GRP;
    const int t = idx / GRP;
    const int r = t & (H_IN - 1);
    const int b = t >> 7;

    const float xsc = 239.0f / 1919.0f;
    const float ysc = 127.0f / 1023.0f;

    // ---- hoisted x-geometry for 8 contiguous output pixels ----
    const int ox0 = g * 8;
    const int q = (ox0 * 239) / 1919;            // exact base input cell
    float wx[8];
    bool  hi[8];
#pragma unroll
    for (int k = 0; k < 8; k++) {
        const float xf = (float)(ox0 + k) * xsc;
        const int x0 = (int)xf;
        wx[k] = xf - (float)x0;
        hi[k] = (x0 > q);                        // pixel lies in cell q+1
    }

    // ---- pred window (2 rows x 3 cols) into registers; clamped edges ----
    const int q1 = min(q + 1, W_IN - 1);
    const int q2 = min(q + 2, W_IN - 1);
    const int r1 = min(r + 1, H_IN - 1);
    const float* __restrict__ p0r = g_pred + (b * H_IN + r)  * W_IN;
    const float* __restrict__ p1r = g_pred + (b * H_IN + r1) * W_IN;
    const float p00 = __ldg(p0r + q), p01 = __ldg(p0r + q1), p02 = __ldg(p0r + q2);
    const float D0 = __ldg(p1r + q)  - p00;
    const float D1 = __ldg(p1r + q1) - p01;
    const float D2 = __ldg(p1r + q2) - p02;

    // ---- output rows owned by input row r: floor(oy*127/1023) == r ----
    const int oys = (r * (H_OUT - 1) + (H_IN - 2)) / (H_IN - 1);
    const int oye = min(H_OUT - 1,
        ((r + 1) * (H_OUT - 1) + (H_IN - 2)) / (H_IN - 1) - 1);

    float4* __restrict__ out4 =
        (float4*)out + (size_t)b * H_OUT * W4 + g * 2;

    for (int oy = oys; oy <= oye; oy++) {
        const float wy = (float)oy * ysc - (float)r;
        const float v0 = p00 + wy * D0;          // y-lerp (3 FMA)
        const float v1 = p01 + wy * D1;
        const float v2 = p02 + wy * D2;
        const float d01 = v1 - v0;
        const float d12 = v2 - v1;

        float4 o0, o1;
#pragma unroll
        for (int k = 0; k < 8; k++) {
            const float base = hi[k] ? v1 : v0;
            const float del  = hi[k] ? d12 : d01;
            const float val  = base + wx[k] * del;
            if (k < 4) ((float*)&o0)[k]     = val;
            else       ((float*)&o1)[k - 4] = val;
        }
        float4* __restrict__ orow = out4 + (size_t)oy * W4;
        orow[0] = o0;
        orow[1] = o1;
    }
}

extern "C" void kernel_launch(void* const* d_in, const int* in_sizes, int n_in,
                              void* d_out, int out_size)
{
    const float* feat_l = (const float*)d_in[0];
    const float* feat_r = (const float*)d_in[1];
    float* out = (float*)d_out;

    disp_kernel<<<BATCH * H_IN, 256>>>(feat_l, feat_r);

    const int total = BATCH * H_IN * GRP;        // 491,520 = 1920 * 256
    resize_kernel<<<total / 256, 256>>>(out);
}

// round 7
// speedup vs baseline: 1.6079x; 1.6079x over previous
#include <cuda_runtime.h>

// Problem constants (fixed by setup_inputs)
#define BATCH   16
#define CHAN    4
#define H_IN    128
#define W_IN    240
#define MAXD    24
#define H_OUT   1024
#define W_OUT   1920
#define W4      (W_OUT / 4)     // 480
#define HW      (H_IN * W_IN)

// Low-res disparity prediction scratch (pred * 8): 16*128*240 floats ≈ 2 MB.
__device__ float g_pred[BATCH * H_IN * W_IN];

// ---------------------------------------------------------------------------
// K1: cost volume + softmax expectation. One block per (b, row-pair).
// Left pixel lives in registers; right row staged via 4 coalesced LDG +
// one STS.128. Unshifted softmax (cost >= 0 -> exp in (0,1], no overflow).
// ---------------------------------------------------------------------------
__global__ __launch_bounds__(512) void disp_kernel(
    const float* __restrict__ fl, const float* __restrict__ fr)
{
    const int pair = blockIdx.x;         // b*64 + yp
    const int b  = pair >> 6;
    const int yp = pair & 63;
    const int half = threadIdx.x >> 8;   // row within pair
    const int x    = threadIdx.x & 255;
    const int y = yp * 2 + half;

    __shared__ float4 sr4[2][W_IN];

    float4 L;
    if (x < W_IN) {
        const size_t rb = (size_t)b * (CHAN * HW) + (size_t)y * W_IN + x;
        float4 R;
        R.x = fr[rb];          R.y = fr[rb + HW];
        R.z = fr[rb + 2 * HW]; R.w = fr[rb + 3 * HW];
        sr4[half][x] = R;
        L.x = fl[rb];          L.y = fl[rb + HW];
        L.z = fl[rb + 2 * HW]; L.w = fl[rb + 3 * HW];
    }
    __syncthreads();

    if (x < W_IN) {
        const float absl = fabsf(L.x) + fabsf(L.y) + fabsf(L.z) + fabsf(L.w);

        float num = 0.0f, den = 0.0f;
#pragma unroll
        for (int d = 0; d < MAXD; d++) {
            const int xs = x - d;
            float c;
            if (xs >= 0) {
                const float4 R = sr4[half][xs];
                c = fabsf(L.x - R.x) + fabsf(L.y - R.y)
                  + fabsf(L.z - R.z) + fabsf(L.w - R.w);
            } else {
                c = absl;                     // zero padding
            }
            const float e = __expf(-c);       // softmax(-cost), unshifted
            den += e;
            num += (float)d * e;
        }
        g_pred[(b * H_IN + y) * W_IN + x] = (num / den) * 8.0f;  // * 1024/128
    }
}

// ---------------------------------------------------------------------------
// K2: bilinear upsample 128x240 -> 1024x1920 (align_corners).
// One thread per (b, input-row r, float4 column g4). 983,040 threads.
// 480 float4/row = 15 warps exactly -> every warp store is 512B contiguous.
// x-geometry + 2x3 pred window hoisted into registers, reused over ~8 rows.
// ---------------------------------------------------------------------------
__global__ __launch_bounds__(256) void resize_kernel(float* __restrict__ out)
{
    const int idx = blockIdx.x * 256 + threadIdx.x;   // exact grid, no guard
    const int g = idx % W4;
    const int t = idx / W4;
    const int r = t & (H_IN - 1);
    const int b = t >> 7;

    const float xsc = 239.0f / 1919.0f;
    const float ysc = 127.0f / 1023.0f;

    // ---- hoisted x-geometry for 4 contiguous output pixels ----
    const int ox0 = g * 4;
    const int q = (ox0 * 239) / 1919;            // exact base input cell
    float wx[4];
    bool  hi[4];
#pragma unroll
    for (int k = 0; k < 4; k++) {
        const float xf = (float)(ox0 + k) * xsc;
        const int x0 = (int)xf;
        wx[k] = xf - (float)x0;
        hi[k] = (x0 > q);                        // pixel lies in cell q+1
    }

    // ---- pred window (2 rows x 3 cols) into registers; clamped edges ----
    const int q1 = min(q + 1, W_IN - 1);
    const int q2 = min(q + 2, W_IN - 1);
    const int r1 = min(r + 1, H_IN - 1);
    const float* __restrict__ p0r = g_pred + (b * H_IN + r)  * W_IN;
    const float* __restrict__ p1r = g_pred + (b * H_IN + r1) * W_IN;
    const float p00 = __ldg(p0r + q), p01 = __ldg(p0r + q1), p02 = __ldg(p0r + q2);
    const float D0 = __ldg(p1r + q)  - p00;
    const float D1 = __ldg(p1r + q1) - p01;
    const float D2 = __ldg(p1r + q2) - p02;

    // ---- output rows owned by input row r: floor(oy*127/1023) == r ----
    const int oys = (r * (H_OUT - 1) + (H_IN - 2)) / (H_IN - 1);
    const int oye = min(H_OUT - 1,
        ((r + 1) * (H_OUT - 1) + (H_IN - 2)) / (H_IN - 1) - 1);

    float4* __restrict__ out4 =
        (float4*)out + (size_t)b * H_OUT * W4 + g;

    for (int oy = oys; oy <= oye; oy++) {
        const float wy = (float)oy * ysc - (float)r;
        const float v0 = p00 + wy * D0;          // y-lerp (3 FMA)
        const float v1 = p01 + wy * D1;
        const float v2 = p02 + wy * D2;
        const float d01 = v1 - v0;
        const float d12 = v2 - v1;

        float4 o;
#pragma unroll
        for (int k = 0; k < 4; k++) {
            const float base = hi[k] ? v1 : v0;
            const float del  = hi[k] ? d12 : d01;
            ((float*)&o)[k] = base + wx[k] * del;
        }
        out4[(size_t)oy * W4] = o;               // warp: 512B contiguous
    }
}

extern "C" void kernel_launch(void* const* d_in, const int* in_sizes, int n_in,
                              void* d_out, int out_size)
{
    const float* feat_l = (const float*)d_in[0];
    const float* feat_r = (const float*)d_in[1];
    float* out = (float*)d_out;

    disp_kernel<<<BATCH * (H_IN / 2), 512>>>(feat_l, feat_r);

    const int total = BATCH * H_IN * W4;         // 983,040
    resize_kernel<<<total / 256, 256>>>(out);
}